// round 15
// baseline (speedup 1.0000x reference)
#include <cuda_runtime.h>
#include <math.h>

#define Bn   4
#define CIN  256
#define CE   64
#define Gn   4
#define Hn   80
#define Wn   80
#define Nn   (Hn*Wn)        // 6400
#define NCH  65             // output chunks: 64 feature (4ch) + 1 norm
#define NS   8              // table slots: strides 1,2,4,...,128
#define EPSV 1e-8f
#define TU   384            // threads for k_up
#define QU   17             // ceil(Nn/TU)
#define TP   1024           // threads for k_pretab

// ---------------- static device scratch ----------------
__device__ float  g_ft   [Bn*Nn*CIN];
__device__ float  g_embt [Bn*Nn*CE];
__device__ float  g_gembt[Bn*Nn*CE];
__device__ float  g_conf [Bn*Nn*Gn];
__device__ float  g_w    [Bn*Gn*Nn];
__device__ float4 g_cC   [Bn*NCH*Nn];
__device__ float4 g_jm4  [Bn*NS*Nn];      // multipliers float4 [b][slot][k]
__device__ float  g_jmP  [Bn*NS*Gn*Nn];   // multipliers planar [b][slot][g][k]
__device__ int    g_janc [Bn*NS*Nn];
__device__ int2   g_rr   [Bn*NS*Nn];      // packed descendant range {lo, hi}
__device__ int    g_inv  [Bn*Nn];
__device__ int    g_ls   [Bn*(Nn+2)];
__device__ int    g_nlvl [Bn];

// ---------------- packed f32x2 FMA ----------------
__device__ __forceinline__ void ffma2(unsigned long long &d,
                                      unsigned long long a,
                                      unsigned long long b) {
    asm("fma.rn.f32x2 %0, %1, %2, %0;" : "+l"(d) : "l"(a), "l"(b));
}

// ---------------- K1: skinny GEMMs via packed f32x2 FMA ----------------
__global__ __launch_bounds__(256) void k_gemm(const float* __restrict__ feat,
                                              const float* __restrict__ guide,
                                              const float* __restrict__ We,
                                              const float* __restrict__ Wc,
                                              const float* __restrict__ Wg) {
    __shared__ char smraw[34816];
    float*  xs = reinterpret_cast<float*>(smraw);
    float2* ws = reinterpret_cast<float2*>(smraw + 16384);
    float*  stage = reinterpret_cast<float*>(smraw);

    int tid = threadIdx.x;
    int os = tid >> 5;
    int nq = tid & 31;
    int n0 = blockIdx.x * 128;
    int b  = blockIdx.y;
    int path = blockIdx.z;

    const float* X = (path == 0 ? feat : guide) + (size_t)b * CIN * Nn;

    unsigned long long acc[9][2];
#pragma unroll
    for (int j = 0; j < 9; ++j) { acc[j][0] = 0ull; acc[j][1] = 0ull; }

    for (int kc = 0; kc < 256; kc += 32) {
        const float* Xb = X + (size_t)kc * Nn + n0;
#pragma unroll
        for (int i = tid; i < 1024; i += 256) {
            int kk = i >> 5, c4 = i & 31;
            *reinterpret_cast<float4*>(&xs[kk * 128 + c4 * 4]) =
                *reinterpret_cast<const float4*>(&Xb[(size_t)kk * Nn + c4 * 4]);
        }
#pragma unroll
        for (int i = tid; i < 2304; i += 256) {
            int o = i >> 5, kk = i & 31;
            float v = 0.f;
            if (path == 0) {
                if (o < 64)       v = We[o * 256 + kc + kk];
                else if (o < 68)  v = Wc[(o - 64) * 256 + kc + kk];
            } else {
                if (o < 64)       v = Wg[o * 256 + kc + kk];
            }
            ws[i] = make_float2(v, v);
        }
        __syncthreads();
#pragma unroll 2
        for (int kk = 0; kk < 32; ++kk) {
            float4 x4 = *reinterpret_cast<const float4*>(&xs[kk * 128 + nq * 4]);
            unsigned long long xlo = *reinterpret_cast<unsigned long long*>(&x4.x);
            unsigned long long xhi = *reinterpret_cast<unsigned long long*>(&x4.z);
#pragma unroll
            for (int j = 0; j < 9; ++j) {
                float2 wv = ws[(os * 9 + j) * 32 + kk];
                unsigned long long wp = *reinterpret_cast<unsigned long long*>(&wv);
                ffma2(acc[j][0], xlo, wp);
                ffma2(acc[j][1], xhi, wp);
            }
        }
        __syncthreads();
    }
#pragma unroll
    for (int j = 0; j < 9; ++j) {
        int o = os * 9 + j;
        if (o < 68) {
            float2 lo = *reinterpret_cast<float2*>(&acc[j][0]);
            float2 hi = *reinterpret_cast<float2*>(&acc[j][1]);
            stage[(nq * 4 + 0) * 68 + o] = lo.x;
            stage[(nq * 4 + 1) * 68 + o] = lo.y;
            stage[(nq * 4 + 2) * 68 + o] = hi.x;
            stage[(nq * 4 + 3) * 68 + o] = hi.y;
        }
    }
    __syncthreads();
    float* outt = (path == 0) ? g_embt : g_gembt;
#pragma unroll
    for (int i = tid; i < 2048; i += 256) {
        int n = i >> 4, c4 = i & 15;
        float4 v = *reinterpret_cast<float4*>(&stage[n * 68 + c4 * 4]);
        *reinterpret_cast<float4*>(&outt[((size_t)b * Nn + n0 + n) * 64 + c4 * 4]) = v;
    }
    if (path == 0) {
#pragma unroll
        for (int i = tid; i < 512; i += 256) {
            int n = i >> 2, gg = i & 3;
            float x = stage[n * 68 + 64 + gg];
            g_conf[((size_t)b * Nn + n0 + n) * 4 + gg] = 1.f / (1.f + expf(-x));
        }
    }
}

// ---------------- K2: edge weights, 2 threads per node ----------------
__global__ __launch_bounds__(256) void k_w(const int* __restrict__ order,
                                           const int* __restrict__ parent,
                                           const float* __restrict__ beta) {
    int b = blockIdx.y;
    int idx = blockIdx.x * 256 + threadIdx.x;
    int k = idx >> 1, half = idx & 1;
    if (k >= Nn) return;
    int n1 = order[b * Nn + k];
    int p  = parent[b * Nn + k];
    int n0 = order[b * Nn + p];
    int coff = half * 32;
    const float4* e1 = reinterpret_cast<const float4*>(g_embt  + ((size_t)b * Nn + n1) * 64 + coff);
    const float4* e0 = reinterpret_cast<const float4*>(g_embt  + ((size_t)b * Nn + n0) * 64 + coff);
    const float4* q1 = reinterpret_cast<const float4*>(g_gembt + ((size_t)b * Nn + n1) * 64 + coff);
    const float4* q0 = reinterpret_cast<const float4*>(g_gembt + ((size_t)b * Nn + n0) * 64 + coff);
    float d[2] = {0.f, 0.f};
#pragma unroll
    for (int i = 0; i < 8; ++i) {
        float4 a = e1[i], c = e0[i];
        float dx = a.x - c.x, dy = a.y - c.y, dz = a.z - c.z, dw = a.w - c.w;
        d[i >> 2] += dx * dx + dy * dy + dz * dz + dw * dw;
    }
#pragma unroll
    for (int i = 0; i < 8; ++i) {
        float4 a = q1[i], c = q0[i];
        float dx = a.x - c.x, dy = a.y - c.y, dz = a.z - c.z, dw = a.w - c.w;
        d[i >> 2] += dx * dx + dy * dy + dz * dz + dw * dw;
    }
#pragma unroll
    for (int j = 0; j < 2; ++j) {
        int g = half * 2 + j;
        float bb = beta[g];
        g_w[((size_t)b * 4 + g) * Nn + k] = expf(-(d[j] + bb * bb));
    }
}

// ---------------- K3: fused transpose + levels + jump tables (smem doubling) ----------------
__global__ __launch_bounds__(TP) void k_pretab(const float* __restrict__ feat,
                                               const int* __restrict__ order,
                                               const int* __restrict__ parent) {
    extern __shared__ int sh[];
    int bid = blockIdx.x;
    int tid = threadIdx.x;

    if (bid < 6400) {
        __shared__ float t[32][33];
        int b = bid / 1600;
        int r2 = bid - b * 1600;
        int c0 = (r2 / 200) * 32;
        int n0 = (r2 % 200) * 32;
        int tx = tid & 31, ty = tid >> 5;
        const float* src = feat + ((size_t)b * CIN + c0) * Nn + n0;
        t[ty][tx] = src[(size_t)ty * Nn + tx];
        __syncthreads();
        float* dst = g_ft + ((size_t)b * Nn + n0) * CIN + c0;
        dst[(size_t)ty * CIN + tx] = t[tx][ty];
        return;
    }

    if (bid < 6404) {
        // -------- levels role --------
        int* a0 = sh;
        int* a1 = sh + Nn;
        int* l0 = sh + 2 * Nn;
        int* l1 = sh + 3 * Nn;
        __shared__ int s_more;
        int b = bid - 6400;
        const int* pp = parent + b * Nn;
        const int* od = order + b * Nn;
        for (int k = tid; k < Nn; k += TP) {
            a0[k] = pp[k];
            l0[k] = (k == 0) ? 0 : 1;
            g_inv[b * Nn + od[k]] = k;
        }
        __syncthreads();
        int* aa = a0; int* ab = a1; int* la = l0; int* lb = l1;
        for (int it = 0; it < 13; ++it) {
            if (tid == 0) s_more = 0;
            __syncthreads();
            int any = 0;
            for (int k = tid; k < Nn; k += TP) {
                int a = aa[k];
                lb[k] = la[k] + la[a];
                int na = aa[a];
                ab[k] = na;
                any |= na;
            }
            if (any) s_more = 1;
            __syncthreads();
            int* tmp = aa; aa = ab; ab = tmp;
            tmp = la; la = lb; lb = tmp;
            if (!s_more) break;
        }
        int* ls = g_ls + b * (Nn + 2);
        for (int k = tid; k < Nn; k += TP) {
            if (k == 0) ls[0] = 0;
            else if (la[k] != la[k - 1]) ls[la[k]] = k;
            if (k == Nn - 1) { g_nlvl[b] = la[k] + 1; ls[la[k] + 1] = Nn; }
        }
        return;
    }

    // -------- tables role: smem-resident doubling, slots 0..7 --------
    {
        int b = bid - 6404;
        const int* pp = parent + b * Nn;
        int*    ancp = sh;                                        // [Nn] current anc
        float4* jmp  = reinterpret_cast<float4*>(sh + Nn);        // [Nn] current m
        int*    ganc = g_janc + (size_t)b * NS * Nn;
        float4* gjm4 = g_jm4  + (size_t)b * NS * Nn;
        float*  gjmP = g_jmP  + (size_t)b * NS * Gn * Nn;
        int2*   grr  = g_rr   + (size_t)b * NS * Nn;

        // slot 0
        for (int k = tid; k < Nn; k += TP) {
            ancp[k] = pp[k];
            float4 mv;
            mv.x = (k == 0) ? 0.f : g_w[((size_t)b * 4 + 0) * Nn + k];
            mv.y = (k == 0) ? 0.f : g_w[((size_t)b * 4 + 1) * Nn + k];
            mv.z = (k == 0) ? 0.f : g_w[((size_t)b * 4 + 2) * Nn + k];
            mv.w = (k == 0) ? 0.f : g_w[((size_t)b * 4 + 3) * Nn + k];
            jmp[k] = mv;
        }
        __syncthreads();

        for (int s = 0; s < NS; ++s) {
            // store current (anc, m) as slot s + planar + ranges
            for (int k = tid; k < Nn; k += TP) {
                int a = ancp[k];
                float4 m = jmp[k];
                ganc[s * Nn + k] = a;
                gjm4[s * Nn + k] = m;
                gjmP[(s * Gn + 0) * Nn + k] = m.x;
                gjmP[(s * Gn + 1) * Nn + k] = m.y;
                gjmP[(s * Gn + 2) * Nn + k] = m.z;
                gjmP[(s * Gn + 3) * Nn + k] = m.w;
                grr[s * Nn + k] = make_int2(0, 0);
            }
            __syncthreads();
            for (int j = tid; j < Nn; j += TP) {
                int a  = ancp[j];
                int ap = (j > 0) ? ancp[j - 1] : -1;
                if (a != ap) {
                    grr[s * Nn + a].x = j;
                    if (j > 0) grr[s * Nn + ap].y = j;
                }
                if (j == Nn - 1) grr[s * Nn + a].y = Nn;
            }
            if (s == NS - 1) break;
            // doubling: stage in regs (reads), barrier, write
            int na[7]; float4 nm[7];
#pragma unroll
            for (int i = 0; i < 7; ++i) {
                int k = tid + i * TP;
                if (k < Nn) {
                    int a = ancp[k];
                    na[i] = ancp[a];
                    float4 mk = jmp[k];
                    float4 ma = jmp[a];
                    nm[i] = make_float4(mk.x * ma.x, mk.y * ma.y, mk.z * ma.z, mk.w * ma.w);
                }
            }
            __syncthreads();
#pragma unroll
            for (int i = 0; i < 7; ++i) {
                int k = tid + i * TP;
                if (k < Nn) { ancp[k] = na[i]; jmp[k] = nm[i]; }
            }
            __syncthreads();
        }
    }
}

// ---------------- K4: fused up + down sweep — paired chunks, register-primary ----------------
// grid (34, Bn): p<32 feature pair (g=p>>3, quads p&7 and (p&7)+8); p>=32 norm pair (groups 2(p-32), +1)
__global__ __launch_bounds__(TU) void k_up(const int* __restrict__ order) {
    extern __shared__ float4 smb[];
    float4* bufA = smb;        // [Nn]
    float4* bufB = smb + Nn;   // [Nn]
    __shared__ int sls[64];
    __shared__ int s_rlo[8], s_rhi[8];
    __shared__ int s_nlvl;
    int p = blockIdx.x, b = blockIdx.y;
    bool isNorm = (p >= 32);
    int gA, gB, qqA, qqB;
    if (!isNorm) { gA = p >> 3; gB = gA; qqA = p & 7; qqB = qqA + 8; }
    else         { gA = (p - 32) * 2; gB = gA + 1; qqA = 0; qqB = 0; }
    int tid = threadIdx.x;
    if (tid == 0) s_nlvl = g_nlvl[b];
    __syncthreads();
    int nlvl = s_nlvl;
    int nb = (nlvl + 127) / 128;
    const int* gls = g_ls + b * (Nn + 2);
    for (int i = tid; i <= nb; i += TU) {
        int lev = 128 * i;
        sls[i] = (lev == 0) ? 0 : ((lev >= nlvl) ? Nn : gls[lev]);
    }
    if (tid < 8) {
        int sv = 1 << tid;
        s_rlo[tid] = (sv < nlvl) ? gls[sv] : Nn;
        s_rhi[tid] = (sv < nlvl) ? gls[sv + 1] : Nn;
    }

    // init values in registers
    const int* od = order + b * Nn;
    float4 vA[QU], vB[QU];
#pragma unroll
    for (int q = 0; q < QU; ++q) {
        int k = tid + TU * q;
        if (k < Nn) {
            int n = od[k];
            if (!isNorm) {
                float cf = g_conf[((size_t)b * Nn + n) * 4 + gA];
                const float* fr = g_ft + ((size_t)b * Nn + n) * CIN + gA * 64;
                float4 a = *reinterpret_cast<const float4*>(fr + qqA * 4);
                float4 c = *reinterpret_cast<const float4*>(fr + qqB * 4);
                vA[q] = make_float4(a.x * cf, a.y * cf, a.z * cf, a.w * cf);
                vB[q] = make_float4(c.x * cf, c.y * cf, c.z * cf, c.w * cf);
            } else {
                const float* cf4 = g_conf + ((size_t)b * Nn + n) * 4;
                vA[q] = make_float4(cf4[gA], 0.f, 0.f, 0.f);
                vB[q] = make_float4(cf4[gB], 0.f, 0.f, 0.f);
            }
        } else { vA[q] = make_float4(0.f,0.f,0.f,0.f); vB[q] = vA[q]; }
    }

    const int2*  rrb  = g_rr   + (size_t)b * NS * Nn;
    const int*   ancb = g_janc + (size_t)b * NS * Nn;
    const float* mA   = g_jmP  + (size_t)b * NS * Gn * Nn + (size_t)gA * Nn;
    const float* mB   = g_jmP  + (size_t)b * NS * Gn * Nn + (size_t)gB * Nn;

    // ---- 7 factor passes ----
    for (int s = 0; s < 7; ++s) {
        const float* mAs = mA + (size_t)s * Gn * Nn;
        const float* mBs = mB + (size_t)s * Gn * Nn;
        const int2* rr = rrb + s * Nn;
        __syncthreads();
#pragma unroll
        for (int q = 0; q < QU; ++q) {
            int k = tid + TU * q;
            if (k < Nn) {
                float ma = __ldg(&mAs[k]);
                float mb = __ldg(&mBs[k]);
                float4 a = vA[q], c = vB[q];
                bufA[k] = make_float4(ma * a.x, ma * a.y, ma * a.z, ma * a.w);
                bufB[k] = make_float4(mb * c.x, mb * c.y, mb * c.z, mb * c.w);
            }
        }
        __syncthreads();
#pragma unroll
        for (int q = 0; q < QU; ++q) {
            int k = tid + TU * q;
            if (k < Nn) {
                int lo, hi;
                if (k == 0) { lo = s_rlo[s]; hi = s_rhi[s]; }
                else { int2 r = __ldg(&rr[k]); lo = r.x; hi = r.y; }
                float4 aA = vA[q], aB = vB[q];
                for (int j = lo; j < hi; ++j) {
                    float4 xa = bufA[j];
                    float4 xb = bufB[j];
                    aA.x += xa.x; aA.y += xa.y; aA.z += xa.z; aA.w += xa.w;
                    aB.x += xb.x; aB.y += xb.y; aB.z += xb.z; aB.w += xb.w;
                }
                vA[q] = aA; vB[q] = aB;
            }
        }
    }

    // ---- stride-128 tail solve, deep -> shallow ----
    {
        const int2* rr7 = rrb + 7 * Nn;
        const float* mA7 = mA + (size_t)7 * Gn * Nn;
        const float* mB7 = mB + (size_t)7 * Gn * Nn;
        __syncthreads();
#pragma unroll
        for (int q = 0; q < QU; ++q) {
            int k = tid + TU * q;
            if (k < Nn) {
                float ma = __ldg(&mA7[k]);
                float mb = __ldg(&mB7[k]);
                float4 a = vA[q], c = vB[q];
                bufA[k] = make_float4(ma * a.x, ma * a.y, ma * a.z, ma * a.w);
                bufB[k] = make_float4(mb * c.x, mb * c.y, mb * c.z, mb * c.w);
            }
        }
        __syncthreads();
        for (int blk = nb - 2; blk >= 0; --blk) {
            int s0 = sls[blk], e0 = sls[blk + 1];
#pragma unroll
            for (int q = 0; q < QU; ++q) {
                int k = tid + TU * q;
                if (k >= s0 && k < e0) {
                    int lo, hi;
                    if (k == 0) { lo = s_rlo[7]; hi = s_rhi[7]; }
                    else { int2 r = __ldg(&rr7[k]); lo = r.x; hi = r.y; }
                    float4 aA = vA[q], aB = vB[q];
                    for (int j = lo; j < hi; ++j) {
                        float4 xa = bufA[j];
                        float4 xb = bufB[j];
                        aA.x += xa.x; aA.y += xa.y; aA.z += xa.z; aA.w += xa.w;
                        aB.x += xb.x; aB.y += xb.y; aB.z += xb.z; aB.w += xb.w;
                    }
                    vA[q] = aA; vB[q] = aB;
                    float ma = __ldg(&mA7[k]);
                    float mb = __ldg(&mB7[k]);
                    bufA[k] = make_float4(ma * aA.x, ma * aA.y, ma * aA.z, ma * aA.w);
                    bufB[k] = make_float4(mb * aB.x, mb * aB.y, mb * aB.z, mb * aB.w);
                }
            }
            __syncthreads();
        }
    }

    // ---- c1 = (1 - w^2) * agg ----
#pragma unroll
    for (int q = 0; q < QU; ++q) {
        int k = tid + TU * q;
        if (k < Nn) {
            float wa = __ldg(&mA[k]);
            float wb = __ldg(&mB[k]);
            float fa = 1.f - wa * wa;
            float fb = 1.f - wb * wb;
            vA[q].x *= fa; vA[q].y *= fa; vA[q].z *= fa; vA[q].w *= fa;
            vB[q].x *= fb; vB[q].y *= fb; vB[q].z *= fb; vB[q].w *= fb;
        }
    }

    // ---- 7 compose passes ----
    for (int s = 0; s < 7; ++s) {
        const int* anc = ancb + s * Nn;
        const float* mAs = mA + (size_t)s * Gn * Nn;
        const float* mBs = mB + (size_t)s * Gn * Nn;
        __syncthreads();
#pragma unroll
        for (int q = 0; q < QU; ++q) {
            int k = tid + TU * q;
            if (k < Nn) { bufA[k] = vA[q]; bufB[k] = vB[q]; }
        }
        __syncthreads();
#pragma unroll
        for (int q = 0; q < QU; ++q) {
            int k = tid + TU * q;
            if (k < Nn) {
                int a = __ldg(&anc[k]);
                float ma = __ldg(&mAs[k]);
                float mb = __ldg(&mBs[k]);
                float4 ca = bufA[a];
                float4 cb = bufB[a];
                vA[q].x += ma * ca.x; vA[q].y += ma * ca.y;
                vA[q].z += ma * ca.z; vA[q].w += ma * ca.w;
                vB[q].x += mb * cb.x; vB[q].y += mb * cb.y;
                vB[q].z += mb * cb.z; vB[q].w += mb * cb.w;
            }
        }
    }

    // ---- fused down-sweep: out[k] = c128[k] + m128*out[anc128], 128 levels/phase ----
    {
        const int* anc7 = ancb + 7 * Nn;
        const float* mA7 = mA + (size_t)7 * Gn * Nn;
        const float* mB7 = mB + (size_t)7 * Gn * Nn;
        __syncthreads();
        for (int t = 0; t < nb; ++t) {
            int s0 = sls[t], e0 = sls[t + 1];
#pragma unroll
            for (int q = 0; q < QU; ++q) {
                int k = tid + TU * q;
                if (k >= s0 && k < e0) {
                    float4 oA = vA[q], oB = vB[q];
                    if (t > 0) {
                        int a = __ldg(&anc7[k]);
                        float ma = __ldg(&mA7[k]);
                        float mb = __ldg(&mB7[k]);
                        float4 za = bufA[a];
                        float4 zb = bufB[a];
                        oA.x += ma * za.x; oA.y += ma * za.y;
                        oA.z += ma * za.z; oA.w += ma * za.w;
                        oB.x += mb * zb.x; oB.y += mb * zb.y;
                        oB.z += mb * zb.z; oB.w += mb * zb.w;
                    }
                    bufA[k] = oA; bufB[k] = oB;
                }
            }
            __syncthreads();
        }
    }

    // writeback final filtered values
    if (!isNorm) {
        float4* ccA = g_cC + ((size_t)b * NCH + gA * 16 + qqA) * Nn;
        float4* ccB = g_cC + ((size_t)b * NCH + gA * 16 + qqB) * Nn;
        for (int k = tid; k < Nn; k += TU) { ccA[k] = bufA[k]; ccB[k] = bufB[k]; }
    } else {
        float* cc = reinterpret_cast<float*>(g_cC + ((size_t)b * NCH + 64) * Nn);
        for (int k = tid; k < Nn; k += TU) {
            cc[k * 4 + gA] = bufA[k].x;
            cc[k * 4 + gB] = bufB[k].x;
        }
    }
}

// ---------------- K6: normalize + un-permute + residual ----------------
__global__ __launch_bounds__(256) void k_final(const float* __restrict__ feat,
                                               const float* __restrict__ gammap,
                                               float* __restrict__ out) {
    __shared__ float tile[32 * 65 * 4];
    __shared__ int kq[32];
    int b = blockIdx.y, n0 = blockIdx.x * 32;
    int tid = threadIdx.x;
    if (tid < 32) kq[tid] = g_inv[b * Nn + n0 + tid];
    __syncthreads();
    float4* tile4 = reinterpret_cast<float4*>(tile);
    for (int i = tid; i < 32 * 65; i += 256) {
        int r = i / 65, ci = i - r * 65;
        tile4[i] = g_cC[((size_t)b * NCH + ci) * Nn + kq[r]];
    }
    __syncthreads();
    float gamma = gammap[0];
    int nl = tid & 31;
    int cg = tid >> 5;
    for (int c = cg; c < 256; c += 8) {
        int gr = c >> 6, j = c & 63;
        float filt = tile[(nl * 65 + gr * 16 + (j >> 2)) * 4 + (j & 3)];
        float nrm  = tile[(nl * 65 + 64) * 4 + gr];
        float res = filt / (EPSV + nrm);
        size_t idx = ((size_t)b * CIN + c) * Nn + n0 + nl;
        out[idx] = fmaf(gamma, res, feat[idx]);
    }
}

// ---------------- launcher ----------------
extern "C" void kernel_launch(void* const* d_in, const int* in_sizes, int n_in,
                              void* d_out, int out_size) {
    const float* feature = (const float*)d_in[0];
    const float* guide   = (const float*)d_in[1];
    const float* We      = (const float*)d_in[2];
    const float* Wc      = (const float*)d_in[3];
    const float* Wg      = (const float*)d_in[4];
    const float* beta    = (const float*)d_in[5];
    const float* gamma   = (const float*)d_in[6];
    const int*   order   = (const int*)d_in[7];
    const int*   parent  = (const int*)d_in[8];
    float* out = (float*)d_out;

    // pretab smem: max(levels 4*Nn*4, tables Nn*4 + Nn*16) = Nn*20
    cudaFuncSetAttribute(k_pretab, cudaFuncAttributeMaxDynamicSharedMemorySize, Nn * 20);
    cudaFuncSetAttribute(k_up,     cudaFuncAttributeMaxDynamicSharedMemorySize, 2 * Nn * 16);

    // k_up is this module's 4th launch (ncu -s 5 profiles it)
    k_gemm<<<dim3(Nn / 128, Bn, 2), 256>>>(feature, guide, We, Wc, Wg);
    k_w<<<dim3(Nn * 2 / 256, Bn), 256>>>(order, parent, beta);
    k_pretab<<<6408, TP, Nn * 20>>>(feature, order, parent);
    k_up<<<dim3(34, Bn), TU, 2 * Nn * 16>>>(order);
    k_final<<<dim3(Nn / 32, Bn), 256>>>(feature, gamma, out);
}

// round 17
// speedup vs baseline: 1.0945x; 1.0945x over previous
#include <cuda_runtime.h>
#include <math.h>

#define Bn   4
#define CIN  256
#define CE   64
#define Gn   4
#define Hn   80
#define Wn   80
#define Nn   (Hn*Wn)        // 6400
#define NCH  65             // output chunks: 64 feature (4ch) + 1 norm
#define NS   8              // table slots: strides 1,2,4,...,128
#define EPSV 1e-8f
#define TU   384            // threads for k_up
#define QU   17             // ceil(Nn/TU)
#define TP   1024           // threads for k_tab

// ---------------- static device scratch ----------------
__device__ float  g_ft   [Bn*Nn*CIN];
__device__ float  g_embt [Bn*Nn*CE];
__device__ float  g_gembt[Bn*Nn*CE];
__device__ float  g_conf [Bn*Nn*Gn];
__device__ float  g_w    [Bn*Gn*Nn];
__device__ float4 g_cC   [Bn*NCH*Nn];
__device__ float4 g_jm4  [Bn*NS*Nn];      // multipliers float4 [b][slot][k]
__device__ float  g_jmP  [Bn*NS*Gn*Nn];   // multipliers planar [b][slot][g][k]
__device__ int    g_janc [Bn*NS*Nn];
__device__ int2   g_rr   [Bn*NS*Nn];      // packed descendant range {lo, hi}
__device__ int    g_inv  [Bn*Nn];
__device__ int    g_ls   [Bn*(Nn+2)];
__device__ int    g_nlvl [Bn];

// ---------------- packed f32x2 FMA ----------------
__device__ __forceinline__ void ffma2(unsigned long long &d,
                                      unsigned long long a,
                                      unsigned long long b) {
    asm("fma.rn.f32x2 %0, %1, %2, %0;" : "+l"(d) : "l"(a), "l"(b));
}

// ---------------- K1: skinny GEMMs via packed f32x2 FMA ----------------
__global__ __launch_bounds__(256) void k_gemm(const float* __restrict__ feat,
                                              const float* __restrict__ guide,
                                              const float* __restrict__ We,
                                              const float* __restrict__ Wc,
                                              const float* __restrict__ Wg) {
    __shared__ char smraw[34816];
    float*  xs = reinterpret_cast<float*>(smraw);
    float2* ws = reinterpret_cast<float2*>(smraw + 16384);
    float*  stage = reinterpret_cast<float*>(smraw);

    int tid = threadIdx.x;
    int os = tid >> 5;
    int nq = tid & 31;
    int n0 = blockIdx.x * 128;
    int b  = blockIdx.y;
    int path = blockIdx.z;

    const float* X = (path == 0 ? feat : guide) + (size_t)b * CIN * Nn;

    unsigned long long acc[9][2];
#pragma unroll
    for (int j = 0; j < 9; ++j) { acc[j][0] = 0ull; acc[j][1] = 0ull; }

    for (int kc = 0; kc < 256; kc += 32) {
        const float* Xb = X + (size_t)kc * Nn + n0;
#pragma unroll
        for (int i = tid; i < 1024; i += 256) {
            int kk = i >> 5, c4 = i & 31;
            *reinterpret_cast<float4*>(&xs[kk * 128 + c4 * 4]) =
                *reinterpret_cast<const float4*>(&Xb[(size_t)kk * Nn + c4 * 4]);
        }
#pragma unroll
        for (int i = tid; i < 2304; i += 256) {
            int o = i >> 5, kk = i & 31;
            float v = 0.f;
            if (path == 0) {
                if (o < 64)       v = We[o * 256 + kc + kk];
                else if (o < 68)  v = Wc[(o - 64) * 256 + kc + kk];
            } else {
                if (o < 64)       v = Wg[o * 256 + kc + kk];
            }
            ws[i] = make_float2(v, v);
        }
        __syncthreads();
#pragma unroll 2
        for (int kk = 0; kk < 32; ++kk) {
            float4 x4 = *reinterpret_cast<const float4*>(&xs[kk * 128 + nq * 4]);
            unsigned long long xlo = *reinterpret_cast<unsigned long long*>(&x4.x);
            unsigned long long xhi = *reinterpret_cast<unsigned long long*>(&x4.z);
#pragma unroll
            for (int j = 0; j < 9; ++j) {
                float2 wv = ws[(os * 9 + j) * 32 + kk];
                unsigned long long wp = *reinterpret_cast<unsigned long long*>(&wv);
                ffma2(acc[j][0], xlo, wp);
                ffma2(acc[j][1], xhi, wp);
            }
        }
        __syncthreads();
    }
#pragma unroll
    for (int j = 0; j < 9; ++j) {
        int o = os * 9 + j;
        if (o < 68) {
            float2 lo = *reinterpret_cast<float2*>(&acc[j][0]);
            float2 hi = *reinterpret_cast<float2*>(&acc[j][1]);
            stage[(nq * 4 + 0) * 68 + o] = lo.x;
            stage[(nq * 4 + 1) * 68 + o] = lo.y;
            stage[(nq * 4 + 2) * 68 + o] = hi.x;
            stage[(nq * 4 + 3) * 68 + o] = hi.y;
        }
    }
    __syncthreads();
    float* outt = (path == 0) ? g_embt : g_gembt;
#pragma unroll
    for (int i = tid; i < 2048; i += 256) {
        int n = i >> 4, c4 = i & 15;
        float4 v = *reinterpret_cast<float4*>(&stage[n * 68 + c4 * 4]);
        *reinterpret_cast<float4*>(&outt[((size_t)b * Nn + n0 + n) * 64 + c4 * 4]) = v;
    }
    if (path == 0) {
#pragma unroll
        for (int i = tid; i < 512; i += 256) {
            int n = i >> 2, gg = i & 3;
            float x = stage[n * 68 + 64 + gg];
            g_conf[((size_t)b * Nn + n0 + n) * 4 + gg] = 1.f / (1.f + expf(-x));
        }
    }
}

// ---------------- K2: edge weights, 2 threads per node ----------------
__global__ __launch_bounds__(256) void k_w(const int* __restrict__ order,
                                           const int* __restrict__ parent,
                                           const float* __restrict__ beta) {
    int b = blockIdx.y;
    int idx = blockIdx.x * 256 + threadIdx.x;
    int k = idx >> 1, half = idx & 1;
    if (k >= Nn) return;
    int n1 = order[b * Nn + k];
    int p  = parent[b * Nn + k];
    int n0 = order[b * Nn + p];
    int coff = half * 32;
    const float4* e1 = reinterpret_cast<const float4*>(g_embt  + ((size_t)b * Nn + n1) * 64 + coff);
    const float4* e0 = reinterpret_cast<const float4*>(g_embt  + ((size_t)b * Nn + n0) * 64 + coff);
    const float4* q1 = reinterpret_cast<const float4*>(g_gembt + ((size_t)b * Nn + n1) * 64 + coff);
    const float4* q0 = reinterpret_cast<const float4*>(g_gembt + ((size_t)b * Nn + n0) * 64 + coff);
    float d[2] = {0.f, 0.f};
#pragma unroll
    for (int i = 0; i < 8; ++i) {
        float4 a = e1[i], c = e0[i];
        float dx = a.x - c.x, dy = a.y - c.y, dz = a.z - c.z, dw = a.w - c.w;
        d[i >> 2] += dx * dx + dy * dy + dz * dz + dw * dw;
    }
#pragma unroll
    for (int i = 0; i < 8; ++i) {
        float4 a = q1[i], c = q0[i];
        float dx = a.x - c.x, dy = a.y - c.y, dz = a.z - c.z, dw = a.w - c.w;
        d[i >> 2] += dx * dx + dy * dy + dz * dz + dw * dw;
    }
#pragma unroll
    for (int j = 0; j < 2; ++j) {
        int g = half * 2 + j;
        float bb = beta[g];
        g_w[((size_t)b * 4 + g) * Nn + k] = expf(-(d[j] + bb * bb));
    }
}

// ---------------- K3a: transpose feature (b,c,n) -> (b,n,c), static smem only ----------------
__global__ void k_transpose(const float* __restrict__ f,
                            const int* __restrict__ order) {
    __shared__ float t[32][33];
    int b = blockIdx.z, c0 = blockIdx.y * 32, n0 = blockIdx.x * 32;
    int tx = threadIdx.x, ty = threadIdx.y;         // 32 x 8
    const float* src = f + ((size_t)b * CIN + c0) * Nn + n0;
#pragma unroll
    for (int r = 0; r < 32; r += 8)
        t[ty + r][tx] = src[(size_t)(ty + r) * Nn + tx];
    __syncthreads();
    float* dst = g_ft + ((size_t)b * Nn + n0) * CIN + c0;
#pragma unroll
    for (int r = 0; r < 32; r += 8)
        dst[(size_t)(ty + r) * CIN + tx] = t[tx][ty + r];
    // inverse permutation (once, via the c0==0 slice)
    if (blockIdx.y == 0 && ty == 0) {
        int k = n0 + tx;
        g_inv[b * Nn + order[b * Nn + k]] = k;
    }
}

// ---------------- K3b: levels + jump tables (8 blocks, smem-resident doubling) ----------------
__global__ __launch_bounds__(TP) void k_tab(const int* __restrict__ order,
                                            const int* __restrict__ parent) {
    extern __shared__ int sh[];
    int bid = blockIdx.x;
    int tid = threadIdx.x;

    if (bid < 4) {
        // -------- levels role --------
        int* a0 = sh;
        int* a1 = sh + Nn;
        int* l0 = sh + 2 * Nn;
        int* l1 = sh + 3 * Nn;
        __shared__ int s_more;
        int b = bid;
        const int* pp = parent + b * Nn;
        for (int k = tid; k < Nn; k += TP) {
            a0[k] = pp[k];
            l0[k] = (k == 0) ? 0 : 1;
        }
        __syncthreads();
        int* aa = a0; int* ab = a1; int* la = l0; int* lb = l1;
        for (int it = 0; it < 13; ++it) {
            if (tid == 0) s_more = 0;
            __syncthreads();
            int any = 0;
            for (int k = tid; k < Nn; k += TP) {
                int a = aa[k];
                lb[k] = la[k] + la[a];
                int na = aa[a];
                ab[k] = na;
                any |= na;
            }
            if (any) s_more = 1;
            __syncthreads();
            int* tmp = aa; aa = ab; ab = tmp;
            tmp = la; la = lb; lb = tmp;
            if (!s_more) break;
        }
        int* ls = g_ls + b * (Nn + 2);
        for (int k = tid; k < Nn; k += TP) {
            if (k == 0) ls[0] = 0;
            else if (la[k] != la[k - 1]) ls[la[k]] = k;
            if (k == Nn - 1) { g_nlvl[b] = la[k] + 1; ls[la[k] + 1] = Nn; }
        }
        return;
    }

    // -------- tables role: smem-resident doubling, slots 0..7 --------
    {
        int b = bid - 4;
        const int* pp = parent + b * Nn;
        int*    ancp = sh;                                        // [Nn] current anc
        float4* jmp  = reinterpret_cast<float4*>(sh + Nn);        // [Nn] current m
        int*    ganc = g_janc + (size_t)b * NS * Nn;
        float4* gjm4 = g_jm4  + (size_t)b * NS * Nn;
        float*  gjmP = g_jmP  + (size_t)b * NS * Gn * Nn;
        int2*   grr  = g_rr   + (size_t)b * NS * Nn;

        for (int k = tid; k < Nn; k += TP) {
            ancp[k] = pp[k];
            float4 mv;
            mv.x = (k == 0) ? 0.f : g_w[((size_t)b * 4 + 0) * Nn + k];
            mv.y = (k == 0) ? 0.f : g_w[((size_t)b * 4 + 1) * Nn + k];
            mv.z = (k == 0) ? 0.f : g_w[((size_t)b * 4 + 2) * Nn + k];
            mv.w = (k == 0) ? 0.f : g_w[((size_t)b * 4 + 3) * Nn + k];
            jmp[k] = mv;
        }
        __syncthreads();

        for (int s = 0; s < NS; ++s) {
            for (int k = tid; k < Nn; k += TP) {
                int a = ancp[k];
                float4 m = jmp[k];
                ganc[s * Nn + k] = a;
                gjm4[s * Nn + k] = m;
                gjmP[(s * Gn + 0) * Nn + k] = m.x;
                gjmP[(s * Gn + 1) * Nn + k] = m.y;
                gjmP[(s * Gn + 2) * Nn + k] = m.z;
                gjmP[(s * Gn + 3) * Nn + k] = m.w;
                grr[s * Nn + k] = make_int2(0, 0);
            }
            __syncthreads();
            for (int j = tid; j < Nn; j += TP) {
                int a  = ancp[j];
                int ap = (j > 0) ? ancp[j - 1] : -1;
                if (a != ap) {
                    grr[s * Nn + a].x = j;
                    if (j > 0) grr[s * Nn + ap].y = j;
                }
                if (j == Nn - 1) grr[s * Nn + a].y = Nn;
            }
            if (s == NS - 1) break;
            int na[7]; float4 nm[7];
#pragma unroll
            for (int i = 0; i < 7; ++i) {
                int k = tid + i * TP;
                if (k < Nn) {
                    int a = ancp[k];
                    na[i] = ancp[a];
                    float4 mk = jmp[k];
                    float4 ma = jmp[a];
                    nm[i] = make_float4(mk.x * ma.x, mk.y * ma.y, mk.z * ma.z, mk.w * ma.w);
                }
            }
            __syncthreads();
#pragma unroll
            for (int i = 0; i < 7; ++i) {
                int k = tid + i * TP;
                if (k < Nn) { ancp[k] = na[i]; jmp[k] = nm[i]; }
            }
            __syncthreads();
        }
    }
}

// ---------------- K4: fused up + down sweep — paired chunks, register-primary ----------------
// grid (34, Bn): p<32 feature pair (g=p>>3, quads p&7 and (p&7)+8); p>=32 norm pair
__global__ __launch_bounds__(TU) void k_up(const int* __restrict__ order) {
    extern __shared__ float4 smb[];
    float4* bufA = smb;        // [Nn]
    float4* bufB = smb + Nn;   // [Nn]
    __shared__ int sls[64];
    __shared__ int s_rlo[8], s_rhi[8];
    __shared__ int s_nlvl;
    int p = blockIdx.x, b = blockIdx.y;
    bool isNorm = (p >= 32);
    int gA, gB, qqA, qqB;
    if (!isNorm) { gA = p >> 3; gB = gA; qqA = p & 7; qqB = qqA + 8; }
    else         { gA = (p - 32) * 2; gB = gA + 1; qqA = 0; qqB = 0; }
    int tid = threadIdx.x;
    if (tid == 0) s_nlvl = g_nlvl[b];
    __syncthreads();
    int nlvl = s_nlvl;
    int nb = (nlvl + 127) / 128;
    const int* gls = g_ls + b * (Nn + 2);
    for (int i = tid; i <= nb; i += TU) {
        int lev = 128 * i;
        sls[i] = (lev == 0) ? 0 : ((lev >= nlvl) ? Nn : gls[lev]);
    }
    if (tid < 8) {
        int sv = 1 << tid;
        s_rlo[tid] = (sv < nlvl) ? gls[sv] : Nn;
        s_rhi[tid] = (sv < nlvl) ? gls[sv + 1] : Nn;
    }

    // init values in registers
    const int* od = order + b * Nn;
    float4 vA[QU], vB[QU];
#pragma unroll
    for (int q = 0; q < QU; ++q) {
        int k = tid + TU * q;
        if (k < Nn) {
            int n = od[k];
            if (!isNorm) {
                float cf = g_conf[((size_t)b * Nn + n) * 4 + gA];
                const float* fr = g_ft + ((size_t)b * Nn + n) * CIN + gA * 64;
                float4 a = *reinterpret_cast<const float4*>(fr + qqA * 4);
                float4 c = *reinterpret_cast<const float4*>(fr + qqB * 4);
                vA[q] = make_float4(a.x * cf, a.y * cf, a.z * cf, a.w * cf);
                vB[q] = make_float4(c.x * cf, c.y * cf, c.z * cf, c.w * cf);
            } else {
                const float* cf4 = g_conf + ((size_t)b * Nn + n) * 4;
                vA[q] = make_float4(cf4[gA], 0.f, 0.f, 0.f);
                vB[q] = make_float4(cf4[gB], 0.f, 0.f, 0.f);
            }
        } else { vA[q] = make_float4(0.f,0.f,0.f,0.f); vB[q] = vA[q]; }
    }

    const int2*  rrb  = g_rr   + (size_t)b * NS * Nn;
    const int*   ancb = g_janc + (size_t)b * NS * Nn;
    const float* mA   = g_jmP  + (size_t)b * NS * Gn * Nn + (size_t)gA * Nn;
    const float* mB   = g_jmP  + (size_t)b * NS * Gn * Nn + (size_t)gB * Nn;

    // ---- 7 factor passes ----
    for (int s = 0; s < 7; ++s) {
        const float* mAs = mA + (size_t)s * Gn * Nn;
        const float* mBs = mB + (size_t)s * Gn * Nn;
        const int2* rr = rrb + s * Nn;
        __syncthreads();
#pragma unroll
        for (int q = 0; q < QU; ++q) {
            int k = tid + TU * q;
            if (k < Nn) {
                float ma = __ldg(&mAs[k]);
                float mb = __ldg(&mBs[k]);
                float4 a = vA[q], c = vB[q];
                bufA[k] = make_float4(ma * a.x, ma * a.y, ma * a.z, ma * a.w);
                bufB[k] = make_float4(mb * c.x, mb * c.y, mb * c.z, mb * c.w);
            }
        }
        __syncthreads();
#pragma unroll
        for (int q = 0; q < QU; ++q) {
            int k = tid + TU * q;
            if (k < Nn) {
                int lo, hi;
                if (k == 0) { lo = s_rlo[s]; hi = s_rhi[s]; }
                else { int2 r = __ldg(&rr[k]); lo = r.x; hi = r.y; }
                float4 aA = vA[q], aB = vB[q];
                for (int j = lo; j < hi; ++j) {
                    float4 xa = bufA[j];
                    float4 xb = bufB[j];
                    aA.x += xa.x; aA.y += xa.y; aA.z += xa.z; aA.w += xa.w;
                    aB.x += xb.x; aB.y += xb.y; aB.z += xb.z; aB.w += xb.w;
                }
                vA[q] = aA; vB[q] = aB;
            }
        }
    }

    // ---- stride-128 tail solve, deep -> shallow ----
    {
        const int2* rr7 = rrb + 7 * Nn;
        const float* mA7 = mA + (size_t)7 * Gn * Nn;
        const float* mB7 = mB + (size_t)7 * Gn * Nn;
        __syncthreads();
#pragma unroll
        for (int q = 0; q < QU; ++q) {
            int k = tid + TU * q;
            if (k < Nn) {
                float ma = __ldg(&mA7[k]);
                float mb = __ldg(&mB7[k]);
                float4 a = vA[q], c = vB[q];
                bufA[k] = make_float4(ma * a.x, ma * a.y, ma * a.z, ma * a.w);
                bufB[k] = make_float4(mb * c.x, mb * c.y, mb * c.z, mb * c.w);
            }
        }
        __syncthreads();
        for (int blk = nb - 2; blk >= 0; --blk) {
            int s0 = sls[blk], e0 = sls[blk + 1];
#pragma unroll
            for (int q = 0; q < QU; ++q) {
                int k = tid + TU * q;
                if (k >= s0 && k < e0) {
                    int lo, hi;
                    if (k == 0) { lo = s_rlo[7]; hi = s_rhi[7]; }
                    else { int2 r = __ldg(&rr7[k]); lo = r.x; hi = r.y; }
                    float4 aA = vA[q], aB = vB[q];
                    for (int j = lo; j < hi; ++j) {
                        float4 xa = bufA[j];
                        float4 xb = bufB[j];
                        aA.x += xa.x; aA.y += xa.y; aA.z += xa.z; aA.w += xa.w;
                        aB.x += xb.x; aB.y += xb.y; aB.z += xb.z; aB.w += xb.w;
                    }
                    vA[q] = aA; vB[q] = aB;
                    float ma = __ldg(&mA7[k]);
                    float mb = __ldg(&mB7[k]);
                    bufA[k] = make_float4(ma * aA.x, ma * aA.y, ma * aA.z, ma * aA.w);
                    bufB[k] = make_float4(mb * aB.x, mb * aB.y, mb * aB.z, mb * aB.w);
                }
            }
            __syncthreads();
        }
    }

    // ---- c1 = (1 - w^2) * agg ----
#pragma unroll
    for (int q = 0; q < QU; ++q) {
        int k = tid + TU * q;
        if (k < Nn) {
            float wa = __ldg(&mA[k]);
            float wb = __ldg(&mB[k]);
            float fa = 1.f - wa * wa;
            float fb = 1.f - wb * wb;
            vA[q].x *= fa; vA[q].y *= fa; vA[q].z *= fa; vA[q].w *= fa;
            vB[q].x *= fb; vB[q].y *= fb; vB[q].z *= fb; vB[q].w *= fb;
        }
    }

    // ---- 7 compose passes ----
    for (int s = 0; s < 7; ++s) {
        const int* anc = ancb + s * Nn;
        const float* mAs = mA + (size_t)s * Gn * Nn;
        const float* mBs = mB + (size_t)s * Gn * Nn;
        __syncthreads();
#pragma unroll
        for (int q = 0; q < QU; ++q) {
            int k = tid + TU * q;
            if (k < Nn) { bufA[k] = vA[q]; bufB[k] = vB[q]; }
        }
        __syncthreads();
#pragma unroll
        for (int q = 0; q < QU; ++q) {
            int k = tid + TU * q;
            if (k < Nn) {
                int a = __ldg(&anc[k]);
                float ma = __ldg(&mAs[k]);
                float mb = __ldg(&mBs[k]);
                float4 ca = bufA[a];
                float4 cb = bufB[a];
                vA[q].x += ma * ca.x; vA[q].y += ma * ca.y;
                vA[q].z += ma * ca.z; vA[q].w += ma * ca.w;
                vB[q].x += mb * cb.x; vB[q].y += mb * cb.y;
                vB[q].z += mb * cb.z; vB[q].w += mb * cb.w;
            }
        }
    }

    // ---- fused down-sweep: out[k] = c128[k] + m128*out[anc128], 128 levels/phase ----
    {
        const int* anc7 = ancb + 7 * Nn;
        const float* mA7 = mA + (size_t)7 * Gn * Nn;
        const float* mB7 = mB + (size_t)7 * Gn * Nn;
        __syncthreads();
        for (int t = 0; t < nb; ++t) {
            int s0 = sls[t], e0 = sls[t + 1];
#pragma unroll
            for (int q = 0; q < QU; ++q) {
                int k = tid + TU * q;
                if (k >= s0 && k < e0) {
                    float4 oA = vA[q], oB = vB[q];
                    if (t > 0) {
                        int a = __ldg(&anc7[k]);
                        float ma = __ldg(&mA7[k]);
                        float mb = __ldg(&mB7[k]);
                        float4 za = bufA[a];
                        float4 zb = bufB[a];
                        oA.x += ma * za.x; oA.y += ma * za.y;
                        oA.z += ma * za.z; oA.w += ma * za.w;
                        oB.x += mb * zb.x; oB.y += mb * zb.y;
                        oB.z += mb * zb.z; oB.w += mb * zb.w;
                    }
                    bufA[k] = oA; bufB[k] = oB;
                }
            }
            __syncthreads();
        }
    }

    // writeback final filtered values
    if (!isNorm) {
        float4* ccA = g_cC + ((size_t)b * NCH + gA * 16 + qqA) * Nn;
        float4* ccB = g_cC + ((size_t)b * NCH + gA * 16 + qqB) * Nn;
        for (int k = tid; k < Nn; k += TU) { ccA[k] = bufA[k]; ccB[k] = bufB[k]; }
    } else {
        float* cc = reinterpret_cast<float*>(g_cC + ((size_t)b * NCH + 64) * Nn);
        for (int k = tid; k < Nn; k += TU) {
            cc[k * 4 + gA] = bufA[k].x;
            cc[k * 4 + gB] = bufB[k].x;
        }
    }
}

// ---------------- K6: normalize + un-permute + residual ----------------
__global__ __launch_bounds__(256) void k_final(const float* __restrict__ feat,
                                               const float* __restrict__ gammap,
                                               float* __restrict__ out) {
    __shared__ float tile[32 * 65 * 4];
    __shared__ int kq[32];
    int b = blockIdx.y, n0 = blockIdx.x * 32;
    int tid = threadIdx.x;
    if (tid < 32) kq[tid] = g_inv[b * Nn + n0 + tid];
    __syncthreads();
    float4* tile4 = reinterpret_cast<float4*>(tile);
    for (int i = tid; i < 32 * 65; i += 256) {
        int r = i / 65, ci = i - r * 65;
        tile4[i] = g_cC[((size_t)b * NCH + ci) * Nn + kq[r]];
    }
    __syncthreads();
    float gamma = gammap[0];
    int nl = tid & 31;
    int cg = tid >> 5;
    for (int c = cg; c < 256; c += 8) {
        int gr = c >> 6, j = c & 63;
        float filt = tile[(nl * 65 + gr * 16 + (j >> 2)) * 4 + (j & 3)];
        float nrm  = tile[(nl * 65 + 64) * 4 + gr];
        float res = filt / (EPSV + nrm);
        size_t idx = ((size_t)b * CIN + c) * Nn + n0 + nl;
        out[idx] = fmaf(gamma, res, feat[idx]);
    }
}

// ---------------- launcher ----------------
extern "C" void kernel_launch(void* const* d_in, const int* in_sizes, int n_in,
                              void* d_out, int out_size) {
    const float* feature = (const float*)d_in[0];
    const float* guide   = (const float*)d_in[1];
    const float* We      = (const float*)d_in[2];
    const float* Wc      = (const float*)d_in[3];
    const float* Wg      = (const float*)d_in[4];
    const float* beta    = (const float*)d_in[5];
    const float* gamma   = (const float*)d_in[6];
    const int*   order   = (const int*)d_in[7];
    const int*   parent  = (const int*)d_in[8];
    float* out = (float*)d_out;

    cudaFuncSetAttribute(k_tab, cudaFuncAttributeMaxDynamicSharedMemorySize, Nn * 20);
    cudaFuncSetAttribute(k_up,  cudaFuncAttributeMaxDynamicSharedMemorySize, 2 * Nn * 16);

    // profiled 4th launch = k_tab this round (validate table-build cost)
    k_gemm<<<dim3(Nn / 128, Bn, 2), 256>>>(feature, guide, We, Wc, Wg);
    k_w<<<dim3(Nn * 2 / 256, Bn), 256>>>(order, parent, beta);
    k_transpose<<<dim3(Nn / 32, CIN / 32, Bn), dim3(32, 8)>>>(feature, order);
    k_tab<<<8, TP, Nn * 20>>>(order, parent);
    k_up<<<dim3(34, Bn), TU, 2 * Nn * 16>>>(order);
    k_final<<<dim3(Nn / 32, Bn), 256>>>(feature, gamma, out);
}